// round 4
// baseline (speedup 1.0000x reference)
#include <cuda_runtime.h>
#include <cuda_bf16.h>

// ---------------- static scratch ----------------
__device__ int g_node_off[1025];

__global__ void k_prefix(const int* __restrict__ bn, int B) {
    if (threadIdx.x == 0) {
        int acc = 0;
        g_node_off[0] = 0;
        for (int i = 0; i < B; ++i) { acc += bn[i]; g_node_off[i + 1] = acc; }
    }
}

// ---------------- fast path: smem-privatized per-graph accumulation -------
// Requires G*G == 64 and D == 128 (compile-time smem sizing).
#define GG 64
#define DD 128

__global__ void __launch_bounds__(256) spp_priv_kernel(
    const float* __restrict__ feat,
    const int*   __restrict__ xy,
    float*       __restrict__ out,
    int G, int CPG)
{
    __shared__ float s_acc[2][GG * DD];          // 2 x 32 KB

    const int t    = threadIdx.x;
    const int grp  = t >> 7;                     // 0 / 1
    const int gt   = t & 127;                    // owned feature column
    const int lane = t & 31;

    const int b    = blockIdx.x;
    const int g    = b / CPG;                    // graph id
    const int ch   = b % CPG;                    // chunk within graph

    const int gbeg = g_node_off[g];
    const int glen = g_node_off[g + 1] - gbeg;
    const int cbeg = gbeg + (int)((long long)glen * ch / CPG);
    const int cend = gbeg + (int)((long long)glen * (ch + 1) / CPG);
    const int clen = cend - cbeg;
    const int half = clen >> 1;
    const int nbeg = (grp == 0) ? cbeg : cbeg + half;
    const int nend = (grp == 0) ? cbeg + half : cend;

    // zero private accumulators
    float* accall = &s_acc[0][0];
    #pragma unroll
    for (int i = t; i < 2 * GG * DD; i += 256) accall[i] = 0.f;
    __syncthreads();

    float* acc = s_acc[grp];

    // main loop: 32-node batches; per-lane metadata, shfl broadcast.
    // all 4 warps of a group run identical control flow (redundant meta,
    // disjoint columns) -- no intra-group sync needed.
    for (int base = nbeg; base < nend; base += 32) {
        const int cnt = (nend - base >= 32) ? 32 : (nend - base);
        const int nd  = base + ((lane < cnt) ? lane : (cnt - 1));

        const int r  = __ldg(&xy[3 * nd + 0]);
        const int c  = __ldg(&xy[3 * nd + 1]);
        const int dv = __ldg(&xy[3 * nd + 2]);
        const int   myseg = r * G + c;           // within-graph segment
        const float myinv = 1.0f / (float)dv;

        const float* frow = feat + (size_t)base * DD + gt;

        #pragma unroll 4
        for (int j = 0; j < cnt; ++j) {
            const int   seg = __shfl_sync(0xffffffffu, myseg, j);
            const float inv = __shfl_sync(0xffffffffu, myinv, j);
            const float v   = __ldg(frow + (size_t)j * DD);
            acc[seg * DD + gt] += v * inv;       // LDS+FFMA+STS, race-free
        }
    }
    __syncthreads();

    // merge the two group accumulators, reduce into global (vector RED)
    const float4* a0 = reinterpret_cast<const float4*>(s_acc[0]);
    const float4* a1 = reinterpret_cast<const float4*>(s_acc[1]);
    float* dstg = out + (size_t)g * GG * DD;
    #pragma unroll
    for (int i = t; i < GG * DD / 4; i += 256) {
        float4 u = a0[i];
        float4 v = a1[i];
        u.x += v.x; u.y += v.y; u.z += v.z; u.w += v.w;
        asm volatile("red.global.add.v4.f32 [%0], {%1, %2, %3, %4};"
                     :: "l"(dstg + i * 4), "f"(u.x), "f"(u.y), "f"(u.z), "f"(u.w)
                     : "memory");
    }
}

// ---------------- fallback path (round-2 kernel) ----------------
__device__ __forceinline__ int find_graph(const int* s_off, int B, int node) {
    int lo = 0, hi = B;
    while (hi - lo > 1) {
        int mid = (lo + hi) >> 1;
        if (s_off[mid] <= node) lo = mid; else hi = mid;
    }
    return lo;
}

__global__ void __launch_bounds__(256) spp_pool_fallback(
    const float* __restrict__ feat, const int* __restrict__ xy,
    float* __restrict__ out, int N, int D, int G, int B)
{
    extern __shared__ int s_off[];
    for (int i = threadIdx.x; i <= B; i += blockDim.x) s_off[i] = g_node_off[i];
    __syncthreads();

    const int lane   = threadIdx.x & 31;
    const int warp   = (blockIdx.x * blockDim.x + threadIdx.x) >> 5;
    const int nwarps = (gridDim.x * blockDim.x) >> 5;

    for (long long base = (long long)warp * 32; base < N;
         base += (long long)nwarps * 32) {
        long long mynode = base + lane;
        int nd = (mynode < N) ? (int)mynode : (N - 1);
        const int r  = __ldg(&xy[3 * nd + 0]);
        const int c  = __ldg(&xy[3 * nd + 1]);
        const int dv = __ldg(&xy[3 * nd + 2]);
        int gid = find_graph(s_off, B, nd);
        const int   myseg = (gid * G + r) * G + c;
        const float myinv = 1.0f / (float)dv;
        const int cnt = (N - base >= 32) ? 32 : (int)(N - base);

        for (int j = 0; j < cnt; ++j) {
            const int   seg = __shfl_sync(0xffffffffu, myseg, j);
            const float inv = __shfl_sync(0xffffffffu, myinv, j);
            const float* src = feat + ((size_t)(base + j)) * D;
            for (int d4 = lane; d4 * 4 < D; d4 += 32) {
                float4 v = __ldg(reinterpret_cast<const float4*>(src) + d4);
                v.x *= inv; v.y *= inv; v.z *= inv; v.w *= inv;
                float* dst = out + (size_t)seg * D + d4 * 4;
                asm volatile("red.global.add.v4.f32 [%0], {%1, %2, %3, %4};"
                             :: "l"(dst), "f"(v.x), "f"(v.y), "f"(v.z), "f"(v.w)
                             : "memory");
            }
        }
    }
}

extern "C" void kernel_launch(void* const* d_in, const int* in_sizes, int n_in,
                              void* d_out, int out_size) {
    const float* feat = (const float*)d_in[0];
    const int*   xy   = (const int*)d_in[1];
    const int*   bn   = (const int*)d_in[2];
    float*       out  = (float*)d_out;

    const int B = in_sizes[2];
    const int N = in_sizes[1] / 3;
    const int D = in_sizes[0] / N;
    const int S = out_size / D;        // B*G*G
    const int gg = S / B;
    int G = 1;
    while (G * G < gg) ++G;

    k_prefix<<<1, 32>>>(bn, B);

    // output is accumulated via RED in both paths -> zero it every replay
    cudaMemsetAsync(d_out, 0, (size_t)out_size * sizeof(float), 0);

    const bool fast = (D == DD) && (gg == GG) && (G * G == gg) &&
                      (S == B * gg) && (B <= 1024);

    if (fast) {
        int CPG = (512 + B - 1) / B;          // ~512 CTAs total
        if (CPG < 1) CPG = 1;
        spp_priv_kernel<<<B * CPG, 256>>>(feat, xy, out, G, CPG);
    } else {
        size_t smem = (size_t)(B + 1) * sizeof(int);
        long long batches = ((long long)N + 31) / 32;
        int blocks = (int)((batches + 7) / 8);
        if (blocks > 65535) blocks = 65535;
        spp_pool_fallback<<<blocks, 256, smem>>>(feat, xy, out, N, D, G, B);
    }
}

// round 5
// speedup vs baseline: 3.7205x; 3.7205x over previous
#include <cuda_runtime.h>
#include <cuda_bf16.h>

// ---------------- static scratch ----------------
__device__ int g_node_off[1025];

__global__ void k_prefix(const int* __restrict__ bn, int B) {
    if (threadIdx.x == 0) {
        int acc = 0;
        g_node_off[0] = 0;
        for (int i = 0; i < B; ++i) { acc += bn[i]; g_node_off[i + 1] = acc; }
    }
}

// ---------------- fast path: column-sliced private accumulation ----------
// CTA = (graph, 32-column slice, node chunk). 4 warps, each with a private
// padded accumulator (64 segs x 32 cols, stride 36 floats -> 9216B/warp).
// Hot loop keeps LDG.128 (lane = node-group x float4-slot); intra-warp
// (seg,slot) collisions resolved via __match_any_sync step-serialization.
#define SEG_STRIDE 36          // 32 cols + 4 pad floats (bank rotation)
#define WACC (64 * SEG_STRIDE) // 2304 floats per warp accumulator

__global__ void __launch_bounds__(128) spp_slice_kernel(
    const float* __restrict__ feat,
    const int*   __restrict__ xy,
    float*       __restrict__ out,
    int G, int C)
{
    __shared__ float s_acc[4 * WACC];          // 36,864 B

    const int t    = threadIdx.x;
    const int w    = t >> 5;
    const int lane = t & 31;
    const int grp4 = lane >> 3;                // node group 0..3
    const int slot = lane & 7;                 // float4 slot 0..7

    const int idx   = blockIdx.x;
    const int chunk = idx % C;
    const int slice = (idx / C) & 3;
    const int g     = idx / (4 * C);

    const int gbeg = g_node_off[g];
    const int glen = g_node_off[g + 1] - gbeg;
    const int cbeg = gbeg + (int)((long long)glen * chunk / C);
    const int cend = gbeg + (int)((long long)glen * (chunk + 1) / C);

    // zero accumulators
    float4* z = reinterpret_cast<float4*>(s_acc);
    for (int i = t; i < WACC; i += 128) z[i] = make_float4(0.f, 0.f, 0.f, 0.f);
    __syncthreads();

    float* accw = s_acc + w * WACC;
    const unsigned FULL  = 0xffffffffu;
    const unsigned below = grp4 ? ((1u << (grp4 * 8)) - 1u) : 0u;
    const float*   fbase = feat + (size_t)slice * 32 + (size_t)slot * 4;

    for (int base = cbeg + w * 32; base < cend; base += 128) {
        const int cnt = (cend - base >= 32) ? 32 : (cend - base);
        const int nd  = base + ((lane < cnt) ? lane : (cnt - 1));

        const int rr = __ldg(&xy[3 * nd + 0]);
        const int cc = __ldg(&xy[3 * nd + 1]);
        const int dv = __ldg(&xy[3 * nd + 2]);
        int myseg = rr * G + cc;
        if (lane >= cnt) myseg = -1 - lane;     // unique, never matches real segs
        const float myinv = 1.0f / (float)dv;

        // preload the 8 slice-rows this lane touches (MLP = 8)
        float4 vv[8];
        #pragma unroll
        for (int it = 0; it < 8; ++it) {
            const int nb   = it * 4 + grp4;
            const int node = base + ((nb < cnt) ? nb : (cnt - 1));
            vv[it] = __ldg(reinterpret_cast<const float4*>(fbase + (size_t)node * 128));
        }

        #pragma unroll
        for (int it = 0; it < 8; ++it) {
            const int   nb  = it * 4 + grp4;
            const int   seg = __shfl_sync(FULL, myseg, nb);
            const float inv = __shfl_sync(FULL, myinv, nb);
            const bool  act = (nb < cnt);

            const unsigned mm = __match_any_sync(FULL, seg);
            const int step = __popc(mm & below) >> 3;

            float4 v = vv[it];
            v.x *= inv; v.y *= inv; v.z *= inv; v.w *= inv;
            float4* ap = reinterpret_cast<float4*>(accw + seg * SEG_STRIDE + slot * 4);

            if (__all_sync(FULL, step == 0)) {   // common: 4 distinct segs
                if (act) {
                    float4 a = *ap;
                    a.x += v.x; a.y += v.y; a.z += v.z; a.w += v.w;
                    *ap = a;
                }
            } else {                             // rare: serialize colliders
                #pragma unroll
                for (int st = 0; st < 4; ++st) {
                    if (act && step == st) {
                        float4 a = *ap;
                        a.x += v.x; a.y += v.y; a.z += v.z; a.w += v.w;
                        *ap = a;
                    }
                    __syncwarp();
                }
            }
        }
    }
    __syncthreads();

    // merge 4 warp accumulators, vector-RED into global slab
    float* dstg = out + (size_t)g * 64 * 128 + slice * 32;
    for (int i = t; i < 512; i += 128) {
        const int seg = i >> 3, sl = i & 7;
        float4 s = make_float4(0.f, 0.f, 0.f, 0.f);
        #pragma unroll
        for (int ww = 0; ww < 4; ++ww) {
            float4 a = *reinterpret_cast<float4*>(s_acc + ww * WACC + seg * SEG_STRIDE + sl * 4);
            s.x += a.x; s.y += a.y; s.z += a.z; s.w += a.w;
        }
        asm volatile("red.global.add.v4.f32 [%0], {%1, %2, %3, %4};"
                     :: "l"(dstg + (size_t)seg * 128 + sl * 4),
                        "f"(s.x), "f"(s.y), "f"(s.z), "f"(s.w)
                     : "memory");
    }
}

// ---------------- fallback path (round-2 kernel) ----------------
__device__ __forceinline__ int find_graph(const int* s_off, int B, int node) {
    int lo = 0, hi = B;
    while (hi - lo > 1) {
        int mid = (lo + hi) >> 1;
        if (s_off[mid] <= node) lo = mid; else hi = mid;
    }
    return lo;
}

__global__ void __launch_bounds__(256) spp_pool_fallback(
    const float* __restrict__ feat, const int* __restrict__ xy,
    float* __restrict__ out, int N, int D, int G, int B)
{
    extern __shared__ int s_off[];
    for (int i = threadIdx.x; i <= B; i += blockDim.x) s_off[i] = g_node_off[i];
    __syncthreads();

    const int lane   = threadIdx.x & 31;
    const int warp   = (blockIdx.x * blockDim.x + threadIdx.x) >> 5;
    const int nwarps = (gridDim.x * blockDim.x) >> 5;

    for (long long base = (long long)warp * 32; base < N;
         base += (long long)nwarps * 32) {
        long long mynode = base + lane;
        int nd = (mynode < N) ? (int)mynode : (N - 1);
        const int r  = __ldg(&xy[3 * nd + 0]);
        const int c  = __ldg(&xy[3 * nd + 1]);
        const int dv = __ldg(&xy[3 * nd + 2]);
        int gid = find_graph(s_off, B, nd);
        const int   myseg = (gid * G + r) * G + c;
        const float myinv = 1.0f / (float)dv;
        const int cnt = (N - base >= 32) ? 32 : (int)(N - base);

        for (int j = 0; j < cnt; ++j) {
            const int   seg = __shfl_sync(0xffffffffu, myseg, j);
            const float inv = __shfl_sync(0xffffffffu, myinv, j);
            const float* src = feat + ((size_t)(base + j)) * D;
            for (int d4 = lane; d4 * 4 < D; d4 += 32) {
                float4 v = __ldg(reinterpret_cast<const float4*>(src) + d4);
                v.x *= inv; v.y *= inv; v.z *= inv; v.w *= inv;
                float* dst = out + (size_t)seg * D + d4 * 4;
                asm volatile("red.global.add.v4.f32 [%0], {%1, %2, %3, %4};"
                             :: "l"(dst), "f"(v.x), "f"(v.y), "f"(v.z), "f"(v.w)
                             : "memory");
            }
        }
    }
}

extern "C" void kernel_launch(void* const* d_in, const int* in_sizes, int n_in,
                              void* d_out, int out_size) {
    const float* feat = (const float*)d_in[0];
    const int*   xy   = (const int*)d_in[1];
    const int*   bn   = (const int*)d_in[2];
    float*       out  = (float*)d_out;

    const int B = in_sizes[2];
    const int N = in_sizes[1] / 3;
    const int D = in_sizes[0] / N;
    const int S = out_size / D;        // B*G*G
    const int gg = S / B;
    int G = 1;
    while (G * G < gg) ++G;

    k_prefix<<<1, 32>>>(bn, B);

    // output accumulated via RED in both paths -> zero every replay
    cudaMemsetAsync(d_out, 0, (size_t)out_size * sizeof(float), 0);

    const bool fast = (D == 128) && (gg == 64) && (G == 8) &&
                      (S == B * 64) && (B <= 1024);

    if (fast) {
        int C = 2048 / (B * 4);        // target ~2048 CTAs
        if (C < 1) C = 1;
        spp_slice_kernel<<<B * 4 * C, 128>>>(feat, xy, out, G, C);
    } else {
        size_t smem = (size_t)(B + 1) * sizeof(int);
        long long batches = ((long long)N + 31) / 32;
        int blocks = (int)((batches + 7) / 8);
        if (blocks > 65535) blocks = 65535;
        spp_pool_fallback<<<blocks, 256, smem>>>(feat, xy, out, N, D, G, B);
    }
}